// round 4
// baseline (speedup 1.0000x reference)
#include <cuda_runtime.h>

#define Bn   32
#define Nn   1024
#define MLc  3
#define HIDn 100
#define ODIM 147
#define CK   13
#define CK2  169

// interior tile: 32 rows x 64 cols, block = 256 threads
#define ITH  32
#define ITW  64
#define IXH  46
#define IXW  78
#define IXP  79
#define IRH  44
#define IRW  76
#define IRP  78    // even pitch -> aligned LDS.64 pairs

__device__ float g_w1[Bn][ODIM];
__device__ float g_w2[Bn][ODIM];
__device__ float2 g_W13d[Bn][CK2];   // duplicated (w,w) pairs

typedef unsigned long long u64;

#define FMA2(acc, w, v) asm("fma.rn.f32x2 %0, %1, %2, %0;" : "+l"(acc) : "l"(w), "l"(v))

// ---------------------------------------------------------------------------
// Kernel 0: both MLPs in parallel + composite 13x13 (duplicated). 1 blk/sample.
// ---------------------------------------------------------------------------
__global__ void mlp_kernel(const float* __restrict__ kA,
                           const float* __restrict__ w1a, const float* __restrict__ b1a,
                           const float* __restrict__ w2a, const float* __restrict__ b2a,
                           const float* __restrict__ w1b, const float* __restrict__ b1b,
                           const float* __restrict__ w2b, const float* __restrict__ b2b) {
    const int b = blockIdx.x;
    const int t = threadIdx.x;            // 384 threads
    const int path = t / 192;
    const int ta = t - path * 192;
    __shared__ float skA[9];
    __shared__ float h[2][HIDn];
    __shared__ float sh1[ODIM];
    __shared__ float sh2[ODIM];

    if (t < 9) skA[t] = kA[b * 9 + t];
    __syncthreads();

    const float* W1 = path ? w1b : w1a;
    const float* B1 = path ? b1b : b1a;
    const float* W2 = path ? w2b : w2a;
    const float* B2 = path ? b2b : b2a;

    if (ta < HIDn) {
        float acc = B1[ta];
#pragma unroll
        for (int k = 0; k < 9; k++) acc += skA[k] * W1[k * HIDn + ta];
        h[path][ta] = fmaxf(acc, 0.f);
    }
    __syncthreads();

    if (ta < ODIM) {
        float a0 = B2[ta], a1 = 0.f, a2 = 0.f, a3 = 0.f;
#pragma unroll
        for (int k = 0; k < HIDn; k += 4) {     // 4 chains to hide LDS latency
            a0 += h[path][k + 0] * W2[(k + 0) * ODIM + ta];
            a1 += h[path][k + 1] * W2[(k + 1) * ODIM + ta];
            a2 += h[path][k + 2] * W2[(k + 2) * ODIM + ta];
            a3 += h[path][k + 3] * W2[(k + 3) * ODIM + ta];
        }
        float acc = (a0 + a1) + (a2 + a3);
        if (path) { sh2[ta] = acc; g_w2[b][ta] = acc; }
        else      { sh1[ta] = acc; g_w1[b][ta] = acc; }
    }
    __syncthreads();

    if (t < CK2) {
        int u = t / CK, v = t % CK;
        int i0 = max(0, u - 6), i1 = min(6, u);
        int j0 = max(0, v - 6), j1 = min(6, v);
        float acc = 0.f;
        for (int m = 0; m < MLc; m++)
            for (int i = i0; i <= i1; i++)
                for (int j = j0; j <= j1; j++)
                    acc += sh2[m * 49 + i * 7 + j] * sh1[m * 49 + (u - i) * 7 + (v - j)];
        g_W13d[b][t] = make_float2(acc, acc);
    }
}

// ---------------------------------------------------------------------------
// Kernel 1: composite 13x13 over FULL image, f32x2 path. grid (16,32,B), 256.
// ---------------------------------------------------------------------------
__global__ __launch_bounds__(256)
void interior_kernel(const float* __restrict__ x, const float* __restrict__ f,
                     const float* __restrict__ kA, float* __restrict__ out) {
    const int b   = blockIdx.z;
    const int ty0 = blockIdx.y * ITH;
    const int tx0 = blockIdx.x * ITW;
    const int tid = threadIdx.x;
    const bool edge = (blockIdx.x == 0) | (blockIdx.x == 15) |
                      (blockIdx.y == 0) | (blockIdx.y == 31);

    __shared__ __align__(16) float sx[IXH * IXP];
    __shared__ __align__(16) float sr_e[IRH * IRP];
    __shared__ __align__(16) float sr_o_raw[IRH * IRP + 4];
    __shared__ __align__(8)  u64   sWd[CK2];
    __shared__ float skA[9];
    float* sr_o = sr_o_raw + 4;   // sr_o[i] aliases r[...]; index -1 is raw[3] (safe pad)

    if (tid < CK2) sWd[tid] = reinterpret_cast<const u64*>(g_W13d[b])[tid];
    if (tid < 9)   skA[tid] = kA[b * 9 + tid];

    const float* xb = x + (size_t)b * Nn * Nn;
    const float* fb = f + (size_t)b * Nn * Nn;
    float*       ob = out + (size_t)b * Nn * Nn;

    if (!edge) {
#pragma unroll 1
        for (int p = tid; p < IXH * IXW; p += 256) {
            int u = p / IXW, v = p % IXW;
            sx[u * IXP + v] = xb[(ty0 - 7 + u) * Nn + (tx0 - 7 + v)];
        }
        __syncthreads();
#pragma unroll 1
        for (int p = tid; p < IRH * IRW; p += 256) {
            int u = p / IRW, v = p % IRW;
            float acc = fb[(ty0 - 6 + u) * Nn + (tx0 - 6 + v)];
#pragma unroll
            for (int i = 0; i < 3; i++)
#pragma unroll
                for (int j = 0; j < 3; j++)
                    acc -= skA[i * 3 + j] * sx[(u + i) * IXP + (v + j)];
            sr_e[u * IRP + v] = acc;
            sr_o[u * IRP + v - 1] = acc;   // shifted copy: sr_o[j] = r[j+1]
        }
    } else {
#pragma unroll 1
        for (int p = tid; p < IXH * IXW; p += 256) {
            int u = p / IXW, v = p % IXW;
            int gy = ty0 - 7 + u, gx = tx0 - 7 + v;
            float val = 0.f;
            if (gy >= 0 && gy < Nn && gx >= 0 && gx < Nn) val = xb[gy * Nn + gx];
            sx[u * IXP + v] = val;
        }
        __syncthreads();
#pragma unroll 1
        for (int p = tid; p < IRH * IRW; p += 256) {
            int u = p / IRW, v = p % IRW;
            int gy = ty0 - 6 + u, gx = tx0 - 6 + v;
            float val = 0.f;
            if (gy >= 0 && gy < Nn && gx >= 0 && gx < Nn) {
                float acc = fb[gy * Nn + gx];
#pragma unroll
                for (int i = 0; i < 3; i++)
#pragma unroll
                    for (int j = 0; j < 3; j++)
                        acc -= skA[i * 3 + j] * sx[(u + i) * IXP + (v + j)];
                val = acc;
            }
            sr_e[u * IRP + v] = val;
            sr_o[u * IRP + v - 1] = val;
        }
    }
    __syncthreads();

    // ---- Stage C: out = x + corr13(r, W13); 8-px strip, all-aligned LDS.64 ----
    {
        const int row = tid >> 3;            // 0..31
        const int v0  = (tid & 7) << 3;      // 0..56
        u64 acc[4] = {0ULL, 0ULL, 0ULL, 0ULL};

#pragma unroll 1
        for (int u = 0; u < CK; u++) {
            const u64* peP = reinterpret_cast<const u64*>(&sr_e[(row + u) * IRP + v0]);
            const u64* poP = reinterpret_cast<const u64*>(sr_o + (row + u) * IRP + v0);
            const u64* wr  = &sWd[u * CK];
            u64 pe[10], po[9];
#pragma unroll
            for (int m = 0; m < 10; m++) pe[m] = peP[m];
#pragma unroll
            for (int m = 0; m < 9; m++)  po[m] = poP[m];
#pragma unroll
            for (int vv = 0; vv < 7; vv++) {      // even taps 0,2,...,12
                u64 w = wr[2 * vv];
#pragma unroll
                for (int k = 0; k < 4; k++) FMA2(acc[k], w, pe[vv + k]);
            }
#pragma unroll
            for (int vv = 0; vv < 6; vv++) {      // odd taps 1,3,...,11
                u64 w = wr[2 * vv + 1];
#pragma unroll
                for (int k = 0; k < 4; k++) FMA2(acc[k], w, po[vv + k]);
            }
        }

        float res[8];
#pragma unroll
        for (int k = 0; k < 4; k++)
            asm("mov.b64 {%0,%1}, %2;" : "=f"(res[2 * k]), "=f"(res[2 * k + 1]) : "l"(acc[k]));

        const float* xr = &sx[(row + 7) * IXP + v0 + 7];
        float* op = &ob[(ty0 + row) * Nn + tx0 + v0];
        float4 o0, o1;
        o0.x = xr[0] + res[0];  o0.y = xr[1] + res[1];
        o0.z = xr[2] + res[2];  o0.w = xr[3] + res[3];
        o1.x = xr[4] + res[4];  o1.y = xr[5] + res[5];
        o1.z = xr[6] + res[6];  o1.w = xr[7] + res[7];
        *reinterpret_cast<float4*>(op)     = o0;
        *reinterpret_cast<float4*>(op + 4) = o1;
    }
}

// ---------------------------------------------------------------------------
// Kernel 2: exact two-stage on the 3-px frame. grid (32, B), block 256.
// ---------------------------------------------------------------------------
__global__ __launch_bounds__(256)
void frame_kernel(const float* __restrict__ x, const float* __restrict__ f,
                  const float* __restrict__ kA, float* __restrict__ out) {
    const int b = blockIdx.y;
    const int seg = blockIdx.x;
    int oy0, ox0, OH, OW;
    if (seg < 8)       { oy0 = 0;    OH = 3; ox0 = seg * 128;        OW = 128; }
    else if (seg < 16) { oy0 = 1021; OH = 3; ox0 = (seg - 8) * 128;  OW = 128; }
    else if (seg < 24) { ox0 = 0;    OW = 3; oy0 = 3 + (seg - 16) * 128; OH = min(128, 1021 - oy0); }
    else               { ox0 = 1021; OW = 3; oy0 = 3 + (seg - 24) * 128; OH = min(128, 1021 - oy0); }
    const int TH = OH + 6,  TW = OW + 6;
    const int RH = OH + 12, RW = OW + 12;
    const int XH = OH + 14, XW = OW + 14;
    const int tid = threadIdx.x;

    __shared__ float sx[2414];
    __shared__ float sr[2100];
    __shared__ float st[3 * 1206];
    __shared__ float sw1[ODIM], sw2[ODIM], skA[9];

    if (tid < ODIM) { sw1[tid] = g_w1[b][tid]; sw2[tid] = g_w2[b][tid]; }
    if (tid < 9) skA[tid] = kA[b * 9 + tid];

    const float* xb = x + (size_t)b * Nn * Nn;
    const float* fb = f + (size_t)b * Nn * Nn;
    float*       ob = out + (size_t)b * Nn * Nn;

    for (int p = tid; p < XH * XW; p += 256) {
        int i = p / XW, j = p % XW;
        int gy = oy0 - 7 + i, gx = ox0 - 7 + j;
        sx[p] = (gy >= 0 && gy < Nn && gx >= 0 && gx < Nn) ? xb[gy * Nn + gx] : 0.f;
    }
    __syncthreads();

    for (int p = tid; p < RH * RW; p += 256) {
        int i = p / RW, j = p % RW;
        int gy = oy0 - 6 + i, gx = ox0 - 6 + j;
        float v = 0.f;
        if (gy >= 0 && gy < Nn && gx >= 0 && gx < Nn) {
            v = fb[gy * Nn + gx];
#pragma unroll
            for (int a = 0; a < 3; a++)
#pragma unroll
                for (int c = 0; c < 3; c++)
                    v -= skA[a * 3 + c] * sx[(i + a) * XW + (j + c)];
        }
        sr[p] = v;
    }
    __syncthreads();

    const int TA = TH * TW;
    for (int p = tid; p < 3 * TA; p += 256) {
        int m = p / TA, q = p - m * TA;
        int i = q / TW, j = q % TW;
        int gy = oy0 - 3 + i, gx = ox0 - 3 + j;
        float v = 0.f;
        if (gy >= 0 && gy < Nn && gx >= 0 && gx < Nn) {
#pragma unroll
            for (int a = 0; a < 7; a++)
#pragma unroll
                for (int c = 0; c < 7; c++)
                    v += sw1[m * 49 + a * 7 + c] * sr[(i + a) * RW + (j + c)];
        }
        st[m * TA + q] = v;
    }
    __syncthreads();

    for (int p = tid; p < OH * OW; p += 256) {
        int y = p / OW, xc = p % OW;
        float v = sx[(y + 7) * XW + (xc + 7)];
#pragma unroll
        for (int m = 0; m < MLc; m++)
#pragma unroll
            for (int a = 0; a < 7; a++)
#pragma unroll
                for (int c = 0; c < 7; c++)
                    v += sw2[m * 49 + a * 7 + c] * st[m * TA + (y + a) * TW + (xc + c)];
        ob[(oy0 + y) * Nn + (ox0 + xc)] = v;
    }
}

// ---------------------------------------------------------------------------
extern "C" void kernel_launch(void* const* d_in, const int* in_sizes, int n_in,
                              void* d_out, int out_size) {
    const float* x      = (const float*)d_in[0];
    const float* f      = (const float*)d_in[1];
    const float* kA     = (const float*)d_in[2];
    const float* fc1_w1 = (const float*)d_in[3];
    const float* fc1_b1 = (const float*)d_in[4];
    const float* fc1_w2 = (const float*)d_in[5];
    const float* fc1_b2 = (const float*)d_in[6];
    const float* fc2_w1 = (const float*)d_in[7];
    const float* fc2_b1 = (const float*)d_in[8];
    const float* fc2_w2 = (const float*)d_in[9];
    const float* fc2_b2 = (const float*)d_in[10];
    float* out = (float*)d_out;

    mlp_kernel<<<Bn, 384>>>(kA, fc1_w1, fc1_b1, fc1_w2, fc1_b2,
                            fc2_w1, fc2_b1, fc2_w2, fc2_b2);

    dim3 gi(16, 32, Bn);
    interior_kernel<<<gi, 256>>>(x, f, kA, out);

    dim3 gf(32, Bn);
    frame_kernel<<<gf, 256>>>(x, f, kA, out);
}

// round 5
// speedup vs baseline: 1.4948x; 1.4948x over previous
#include <cuda_runtime.h>

#define Bn   32
#define Nn   1024
#define MLc  3
#define HIDn 100
#define ODIM 147
#define CK   13
#define CK2  169

// interior tile: 32 rows x 64 cols, block = 256 threads (8 warps)
#define ITH  32
#define ITW  64
#define IXH  46
#define IXW  78
#define IXP  79    // odd -> conflict-free scalar row reads
#define IRH  44
#define IRW  76
#define IRP  76    // %4==0 and *19 odd-phase -> conflict-free LDS.128
#define OSP  65    // output staging pitch (row*65 mod 32 = row)

__device__ float g_w1[Bn][ODIM];
__device__ float g_w2[Bn][ODIM];
__device__ float g_W13[Bn][CK2];

// ---------------------------------------------------------------------------
// Kernel 0: both MLPs in parallel + composite 13x13. 1 block / sample.
// ---------------------------------------------------------------------------
__global__ void mlp_kernel(const float* __restrict__ kA,
                           const float* __restrict__ w1a, const float* __restrict__ b1a,
                           const float* __restrict__ w2a, const float* __restrict__ b2a,
                           const float* __restrict__ w1b, const float* __restrict__ b1b,
                           const float* __restrict__ w2b, const float* __restrict__ b2b) {
    const int b = blockIdx.x;
    const int t = threadIdx.x;            // 384 threads
    const int path = t / 192;
    const int ta = t - path * 192;
    __shared__ float skA[9];
    __shared__ float h[2][HIDn];
    __shared__ float sh1[ODIM];
    __shared__ float sh2[ODIM];

    if (t < 9) skA[t] = kA[b * 9 + t];
    __syncthreads();

    const float* W1 = path ? w1b : w1a;
    const float* B1 = path ? b1b : b1a;
    const float* W2 = path ? w2b : w2a;
    const float* B2 = path ? b2b : b2a;

    if (ta < HIDn) {
        float acc = B1[ta];
#pragma unroll
        for (int k = 0; k < 9; k++) acc += skA[k] * W1[k * HIDn + ta];
        h[path][ta] = fmaxf(acc, 0.f);
    }
    __syncthreads();

    if (ta < ODIM) {
        float a0 = B2[ta], a1 = 0.f, a2 = 0.f, a3 = 0.f;
#pragma unroll
        for (int k = 0; k < HIDn; k += 4) {
            a0 += h[path][k + 0] * W2[(k + 0) * ODIM + ta];
            a1 += h[path][k + 1] * W2[(k + 1) * ODIM + ta];
            a2 += h[path][k + 2] * W2[(k + 2) * ODIM + ta];
            a3 += h[path][k + 3] * W2[(k + 3) * ODIM + ta];
        }
        float acc = (a0 + a1) + (a2 + a3);
        if (path) { sh2[ta] = acc; g_w2[b][ta] = acc; }
        else      { sh1[ta] = acc; g_w1[b][ta] = acc; }
    }
    __syncthreads();

    if (t < CK2) {
        int u = t / CK, v = t % CK;
        int i0 = max(0, u - 6), i1 = min(6, u);
        int j0 = max(0, v - 6), j1 = min(6, v);
        float acc = 0.f;
        for (int m = 0; m < MLc; m++)
            for (int i = i0; i <= i1; i++)
                for (int j = j0; j <= j1; j++)
                    acc += sh2[m * 49 + i * 7 + j] * sh1[m * 49 + (u - i) * 7 + (v - j)];
        g_W13[b][t] = acc;
    }
}

// ---------------------------------------------------------------------------
// Kernel 1: composite 13x13 over FULL image. grid (16,32,B), block 256.
// Stage C: lane=row mapping, conflict-free LDS.128; staged coalesced output.
// ---------------------------------------------------------------------------
__global__ __launch_bounds__(256)
void interior_kernel(const float* __restrict__ x, const float* __restrict__ f,
                     const float* __restrict__ kA, float* __restrict__ out) {
    const int b   = blockIdx.z;
    const int ty0 = blockIdx.y * ITH;
    const int tx0 = blockIdx.x * ITW;
    const int tid = threadIdx.x;
    const bool edge = (blockIdx.x == 0) | (blockIdx.x == 15) |
                      (blockIdx.y == 0) | (blockIdx.y == 31);

    __shared__ __align__(16) float sx[IXH * IXP];
    __shared__ __align__(16) float sr[IRH * IRP];   // reused as output staging
    __shared__ float sW[CK2];
    __shared__ float skA[9];

    if (tid < CK2) sW[tid] = g_W13[b][tid];
    if (tid < 9)   skA[tid] = kA[b * 9 + tid];

    const float* xb = x + (size_t)b * Nn * Nn;
    const float* fb = f + (size_t)b * Nn * Nn;
    float*       ob = out + (size_t)b * Nn * Nn;

    if (!edge) {
#pragma unroll 1
        for (int p = tid; p < IXH * IXW; p += 256) {
            int u = p / IXW, v = p % IXW;
            sx[u * IXP + v] = xb[(ty0 - 7 + u) * Nn + (tx0 - 7 + v)];
        }
        __syncthreads();
#pragma unroll 1
        for (int p = tid; p < IRH * IRW; p += 256) {
            int u = p / IRW, v = p % IRW;
            float acc = fb[(ty0 - 6 + u) * Nn + (tx0 - 6 + v)];
#pragma unroll
            for (int i = 0; i < 3; i++)
#pragma unroll
                for (int j = 0; j < 3; j++)
                    acc -= skA[i * 3 + j] * sx[(u + i) * IXP + (v + j)];
            sr[p] = acc;    // p == u*IRP + v since IRP==IRW
        }
    } else {
#pragma unroll 1
        for (int p = tid; p < IXH * IXW; p += 256) {
            int u = p / IXW, v = p % IXW;
            int gy = ty0 - 7 + u, gx = tx0 - 7 + v;
            float val = 0.f;
            if (gy >= 0 && gy < Nn && gx >= 0 && gx < Nn) val = xb[gy * Nn + gx];
            sx[u * IXP + v] = val;
        }
        __syncthreads();
#pragma unroll 1
        for (int p = tid; p < IRH * IRW; p += 256) {
            int u = p / IRW, v = p % IRW;
            int gy = ty0 - 6 + u, gx = tx0 - 6 + v;
            float val = 0.f;
            if (gy >= 0 && gy < Nn && gx >= 0 && gx < Nn) {
                float acc = fb[gy * Nn + gx];
#pragma unroll
                for (int i = 0; i < 3; i++)
#pragma unroll
                    for (int j = 0; j < 3; j++)
                        acc -= skA[i * 3 + j] * sx[(u + i) * IXP + (v + j)];
                val = acc;
            }
            sr[p] = val;
        }
    }
    __syncthreads();

    // ---- Stage C: acc = corr13(r, W13). lane=row, strip=warp. ----
    const int row = tid & 31;            // 0..31  (lane)
    const int v0  = (tid >> 5) << 3;     // warp id * 8 : 0..56
    float acc[8] = {0, 0, 0, 0, 0, 0, 0, 0};
    {
#pragma unroll 1
        for (int u = 0; u < CK; u++) {
            const float4* rp = reinterpret_cast<const float4*>(&sr[(row + u) * IRP + v0]);
            float rv[20];
            float4 q;
#pragma unroll
            for (int m = 0; m < 5; m++) {
                q = rp[m];
                rv[4 * m + 0] = q.x; rv[4 * m + 1] = q.y;
                rv[4 * m + 2] = q.z; rv[4 * m + 3] = q.w;
            }
            const float* wrow = &sW[u * CK];
#pragma unroll
            for (int v = 0; v < CK; v++) {
                float w = wrow[v];
#pragma unroll
                for (int k = 0; k < 8; k++) acc[k] = fmaf(w, rv[v + k], acc[k]);
            }
        }
    }
    __syncthreads();                      // all sr reads done

    // ---- stage output into sr (pitch 65, conflict-free STS) ----
#pragma unroll
    for (int k = 0; k < 8; k++) sr[row * OSP + v0 + k] = acc[k];
    __syncthreads();

    // ---- coalesced store: out = x + G2 ----
#pragma unroll 1
    for (int p = tid; p < ITH * ITW; p += 256) {
        int y = p >> 6, xc = p & 63;
        ob[(ty0 + y) * Nn + (tx0 + xc)] =
            sx[(y + 7) * IXP + (xc + 7)] + sr[y * OSP + xc];
    }
}

// ---------------------------------------------------------------------------
// Kernel 2: exact two-stage on the 3-px frame. grid (32, B), block 256.
// ---------------------------------------------------------------------------
__global__ __launch_bounds__(256)
void frame_kernel(const float* __restrict__ x, const float* __restrict__ f,
                  const float* __restrict__ kA, float* __restrict__ out) {
    const int b = blockIdx.y;
    const int seg = blockIdx.x;
    int oy0, ox0, OH, OW;
    if (seg < 8)       { oy0 = 0;    OH = 3; ox0 = seg * 128;        OW = 128; }
    else if (seg < 16) { oy0 = 1021; OH = 3; ox0 = (seg - 8) * 128;  OW = 128; }
    else if (seg < 24) { ox0 = 0;    OW = 3; oy0 = 3 + (seg - 16) * 128; OH = min(128, 1021 - oy0); }
    else               { ox0 = 1021; OW = 3; oy0 = 3 + (seg - 24) * 128; OH = min(128, 1021 - oy0); }
    const int TH = OH + 6,  TW = OW + 6;
    const int RH = OH + 12, RW = OW + 12;
    const int XH = OH + 14, XW = OW + 14;
    const int tid = threadIdx.x;

    __shared__ float sx[2414];
    __shared__ float sr[2100];
    __shared__ float st[3 * 1206];
    __shared__ float sw1[ODIM], sw2[ODIM], skA[9];

    if (tid < ODIM) { sw1[tid] = g_w1[b][tid]; sw2[tid] = g_w2[b][tid]; }
    if (tid < 9) skA[tid] = kA[b * 9 + tid];

    const float* xb = x + (size_t)b * Nn * Nn;
    const float* fb = f + (size_t)b * Nn * Nn;
    float*       ob = out + (size_t)b * Nn * Nn;

    for (int p = tid; p < XH * XW; p += 256) {
        int i = p / XW, j = p % XW;
        int gy = oy0 - 7 + i, gx = ox0 - 7 + j;
        sx[p] = (gy >= 0 && gy < Nn && gx >= 0 && gx < Nn) ? xb[gy * Nn + gx] : 0.f;
    }
    __syncthreads();

    for (int p = tid; p < RH * RW; p += 256) {
        int i = p / RW, j = p % RW;
        int gy = oy0 - 6 + i, gx = ox0 - 6 + j;
        float v = 0.f;
        if (gy >= 0 && gy < Nn && gx >= 0 && gx < Nn) {
            v = fb[gy * Nn + gx];
#pragma unroll
            for (int a = 0; a < 3; a++)
#pragma unroll
                for (int c = 0; c < 3; c++)
                    v -= skA[a * 3 + c] * sx[(i + a) * XW + (j + c)];
        }
        sr[p] = v;
    }
    __syncthreads();

    const int TA = TH * TW;
    for (int p = tid; p < 3 * TA; p += 256) {
        int m = p / TA, q = p - m * TA;
        int i = q / TW, j = q % TW;
        int gy = oy0 - 3 + i, gx = ox0 - 3 + j;
        float v = 0.f;
        if (gy >= 0 && gy < Nn && gx >= 0 && gx < Nn) {
#pragma unroll
            for (int a = 0; a < 7; a++)
#pragma unroll
                for (int c = 0; c < 7; c++)
                    v += sw1[m * 49 + a * 7 + c] * sr[(i + a) * RW + (j + c)];
        }
        st[m * TA + q] = v;
    }
    __syncthreads();

    for (int p = tid; p < OH * OW; p += 256) {
        int y = p / OW, xc = p % OW;
        float v = sx[(y + 7) * XW + (xc + 7)];
#pragma unroll
        for (int m = 0; m < MLc; m++)
#pragma unroll
            for (int a = 0; a < 7; a++)
#pragma unroll
                for (int c = 0; c < 7; c++)
                    v += sw2[m * 49 + a * 7 + c] * st[m * TA + (y + a) * TW + (xc + c)];
        ob[(oy0 + y) * Nn + (ox0 + xc)] = v;
    }
}

// ---------------------------------------------------------------------------
extern "C" void kernel_launch(void* const* d_in, const int* in_sizes, int n_in,
                              void* d_out, int out_size) {
    const float* x      = (const float*)d_in[0];
    const float* f      = (const float*)d_in[1];
    const float* kA     = (const float*)d_in[2];
    const float* fc1_w1 = (const float*)d_in[3];
    const float* fc1_b1 = (const float*)d_in[4];
    const float* fc1_w2 = (const float*)d_in[5];
    const float* fc1_b2 = (const float*)d_in[6];
    const float* fc2_w1 = (const float*)d_in[7];
    const float* fc2_b1 = (const float*)d_in[8];
    const float* fc2_w2 = (const float*)d_in[9];
    const float* fc2_b2 = (const float*)d_in[10];
    float* out = (float*)d_out;

    mlp_kernel<<<Bn, 384>>>(kA, fc1_w1, fc1_b1, fc1_w2, fc1_b2,
                            fc2_w1, fc2_b1, fc2_w2, fc2_b2);

    dim3 gi(16, 32, Bn);
    interior_kernel<<<gi, 256>>>(x, f, kA, out);

    dim3 gf(32, Bn);
    frame_kernel<<<gf, 256>>>(x, f, kA, out);
}